// round 1
// baseline (speedup 1.0000x reference)
#include <cuda_runtime.h>
#include <cstdint>

#define BATCH 16
#define NPROP 2048
#define NCLS 80
#define NCLS1 81
#define KTOP 2048
#define CAP 16384
#define NWORD 32          // 2048/64
#define SCORE_THR 0.05f
#define IOU_THR 0.5f
#define MAXR 4.135166556742356f
#define OUTK 100

// ---------------- device scratch (no allocations allowed) ----------------
__device__ unsigned long long g_keys[BATCH][CAP];
__device__ int g_cnt[BATCH];
__device__ float g_score[BATCH][KTOP];
__device__ int g_label[BATCH][KTOP];
__device__ float4 g_box[BATCH][KTOP];
__device__ float4 g_sbox[BATCH][KTOP];
__device__ unsigned long long g_mask[BATCH][KTOP][NWORD];

// ---------------- 0: reset counters ----------------
__global__ void k_reset() {
    if (threadIdx.x < BATCH) g_cnt[threadIdx.x] = 0;
}

// ---------------- 1: softmax + threshold compaction ----------------
// one warp per proposal; 81 logits; fg classes 0..79
__global__ void k_softmax_compact(const float* __restrict__ cls) {
    int gw = (blockIdx.x * blockDim.x + threadIdx.x) >> 5;
    int lane = threadIdx.x & 31;
    if (gw >= BATCH * NPROP) return;
    int b = gw >> 11;
    int n = gw & (NPROP - 1);
    const float* x = cls + (size_t)gw * NCLS1;
    float v0 = x[lane];
    float v1 = x[lane + 32];
    float v2 = (lane < 17) ? x[lane + 64] : -3.4e38f;
    float m = fmaxf(fmaxf(v0, v1), v2);
#pragma unroll
    for (int o = 16; o > 0; o >>= 1) m = fmaxf(m, __shfl_xor_sync(0xffffffffu, m, o));
    float e0 = expf(v0 - m);
    float e1 = expf(v1 - m);
    float e2 = (lane < 17) ? expf(v2 - m) : 0.0f;
    float s = e0 + e1 + e2;
#pragma unroll
    for (int o = 16; o > 0; o >>= 1) s += __shfl_xor_sync(0xffffffffu, s, o);

    // class c = lane, lane+32, lane+64(<80)
    float p0 = e0 / s;
    if (p0 > SCORE_THR) {
        int pos = atomicAdd(&g_cnt[b], 1);
        if (pos < CAP) {
            unsigned idx = (unsigned)(n * NCLS + lane);
            g_keys[b][pos] = ((unsigned long long)(~__float_as_uint(p0)) << 32) | idx;
        }
    }
    float p1 = e1 / s;
    if (p1 > SCORE_THR) {
        int pos = atomicAdd(&g_cnt[b], 1);
        if (pos < CAP) {
            unsigned idx = (unsigned)(n * NCLS + lane + 32);
            g_keys[b][pos] = ((unsigned long long)(~__float_as_uint(p1)) << 32) | idx;
        }
    }
    if (lane < 16) {  // c = 64..79 (lane==16 would be background c=80)
        float p2 = e2 / s;
        if (p2 > SCORE_THR) {
            int pos = atomicAdd(&g_cnt[b], 1);
            if (pos < CAP) {
                unsigned idx = (unsigned)(n * NCLS + lane + 64);
                g_keys[b][pos] = ((unsigned long long)(~__float_as_uint(p2)) << 32) | idx;
            }
        }
    }
}

// ---------------- 2: per-image bitonic sort of candidate keys + decode top-2048 ----------------
extern __shared__ unsigned long long sk[];
__global__ void k_sort_decode(const float* __restrict__ reg,
                              const float* __restrict__ props,
                              const int* __restrict__ hw) {
    int b = blockIdx.x;
    int tid = threadIdx.x;
    int nth = blockDim.x;
    int cnt = g_cnt[b];
    if (cnt > CAP) cnt = CAP;
    int P = KTOP;
    while (P < cnt) P <<= 1;   // <= CAP (power of two)

    for (int i = tid; i < P; i += nth)
        sk[i] = (i < cnt) ? g_keys[b][i] : ~0ULL;
    __syncthreads();

    for (int k = 2; k <= P; k <<= 1) {
        for (int j = k >> 1; j > 0; j >>= 1) {
            for (int i = tid; i < P; i += nth) {
                int ixj = i ^ j;
                if (ixj > i) {
                    unsigned long long a = sk[i], c = sk[ixj];
                    bool up = ((i & k) == 0);
                    if ((a > c) == up) { sk[i] = c; sk[ixj] = a; }
                }
            }
            __syncthreads();
        }
    }

    float h = (float)hw[b * 2];
    float w = (float)hw[b * 2 + 1];
    float offmul = fmaxf(w, h) + 1.0f;

    for (int i = tid; i < KTOP; i += nth) {
        unsigned long long key = sk[i];
        if (key == ~0ULL) {  // padding / invalid
            g_score[b][i] = -1.0f;
            g_label[b][i] = -1;
            g_box[b][i] = make_float4(0.f, 0.f, 0.f, 0.f);
            g_sbox[b][i] = make_float4(-1e9f, -1e9f, -1e9f, -1e9f);
            continue;
        }
        float p = __uint_as_float(~(unsigned)(key >> 32));
        unsigned idx = (unsigned)key;
        int n = (int)(idx / NCLS);
        int c = (int)(idx % NCLS);
        const float* pr = props + ((size_t)b * NPROP + n) * 4;
        float p0 = pr[0], p1 = pr[1], p2 = pr[2], p3 = pr[3];
        float px = (p0 + p2) * 0.5f;
        float py = (p1 + p3) * 0.5f;
        float pw = p2 - p0;
        float ph = p3 - p1;
        const float* dd = reg + ((size_t)b * NPROP + n) * (NCLS * 4) + c * 4;
        float dx = dd[0] * 0.1f;
        float dy = dd[1] * 0.1f;
        float dw = fminf(fmaxf(dd[2] * 0.2f, -MAXR), MAXR);
        float dh = fminf(fmaxf(dd[3] * 0.2f, -MAXR), MAXR);
        float gw = pw * expf(dw);
        float gh = ph * expf(dh);
        float gx = px + pw * dx;
        float gy = py + ph * dy;
        float x1 = fminf(fmaxf(gx - 0.5f * gw, 0.f), w);
        float y1 = fminf(fmaxf(gy - 0.5f * gh, 0.f), h);
        float x2 = fminf(fmaxf(gx + 0.5f * gw, 0.f), w);
        float y2 = fminf(fmaxf(gy + 0.5f * gh, 0.f), h);
        float off = (float)c * offmul;
        g_score[b][i] = p;
        g_label[b][i] = c;
        g_box[b][i] = make_float4(x1, y1, x2, y2);
        g_sbox[b][i] = make_float4(x1 + off, y1 + off, x2 + off, y2 + off);
    }
}

// ---------------- 3: IoU suppression bit-matrix ----------------
// block = (64-row tile, image); mask[i][w] bit t set iff j=w*64+t > i and iou>thr
__global__ void k_build_mask() {
    int b = blockIdx.y;
    int tile = blockIdx.x;         // 32 tiles of 64 rows
    __shared__ float4 sb[KTOP];
    for (int i = threadIdx.x; i < KTOP; i += blockDim.x) sb[i] = g_sbox[b][i];
    __syncthreads();

    for (int u = threadIdx.x; u < 64 * NWORD; u += blockDim.x) {
        int r = u >> 5;            // 0..63
        int wdx = u & (NWORD - 1); // 0..31
        int row = tile * 64 + r;
        int jbase = wdx * 64;
        if (jbase + 63 <= row) {   // entire word is j <= row
            g_mask[b][row][wdx] = 0ULL;
            continue;
        }
        float4 a = sb[row];
        float areaA = fmaxf(a.z - a.x, 0.f) * fmaxf(a.w - a.y, 0.f);
        unsigned long long mword = 0ULL;
        int t0 = (row >= jbase) ? (row - jbase + 1) : 0;
        for (int t = t0; t < 64; t++) {
            float4 c = sb[jbase + t];
            float ltx = fmaxf(a.x, c.x);
            float lty = fmaxf(a.y, c.y);
            float rbx = fminf(a.z, c.z);
            float rby = fminf(a.w, c.w);
            float iw = fmaxf(rbx - ltx, 0.f);
            float ih = fmaxf(rby - lty, 0.f);
            float inter = iw * ih;
            float areaB = fmaxf(c.z - c.x, 0.f) * fmaxf(c.w - c.y, 0.f);
            float uni = areaA + areaB - inter;
            if (uni > 0.f && (inter / uni) > IOU_THR) mword |= (1ULL << t);
        }
        g_mask[b][row][wdx] = mword;
    }
}

// ---------------- 4: sequential greedy scan + emit top-100 ----------------
// one warp per image; lane L owns rows [64L, 64L+64)
__global__ void k_scan_out(float* __restrict__ out) {
    int b = blockIdx.x;
    int lane = threadIdx.x;
    __shared__ float ss[KTOP];
    for (int i = lane; i < KTOP; i += 32) ss[i] = g_score[b][i];
    __syncwarp(0xffffffffu);

    unsigned long long validm = 0ULL;
#pragma unroll 8
    for (int t = 0; t < 64; t++)
        if (ss[lane * 64 + t] > SCORE_THR) validm |= (1ULL << t);

    unsigned long long rem = 0ULL;
    unsigned long long avail = validm;

    const int PD = 16;
    unsigned long long pre[PD];
#pragma unroll
    for (int t = 0; t < PD; t++) pre[t] = g_mask[b][t][lane];

    for (int i0 = 0; i0 < KTOP; i0 += PD) {
#pragma unroll
        for (int t = 0; t < PD; t++) {
            int i = i0 + t;
            unsigned long long aw = __shfl_sync(0xffffffffu, avail, i >> 6);
            bool alive = (aw >> (i & 63)) & 1ULL;
            unsigned long long m = pre[t];
            pre[t] = (i + PD < KTOP) ? g_mask[b][i + PD][lane] : 0ULL;
            if (alive) {
                rem |= m;
                avail = validm & ~rem;
            }
        }
    }

    unsigned long long keepm = validm & ~rem;
    int cnt = __popcll(keepm);
    int inc = cnt;
#pragma unroll
    for (int o = 1; o < 32; o <<= 1) {
        int v = __shfl_up_sync(0xffffffffu, inc, o);
        if (lane >= o) inc += v;
    }
    int total = __shfl_sync(0xffffffffu, inc, 31);
    int rank = inc - cnt;  // exclusive prefix

    unsigned long long mm = keepm;
    while (mm) {
        int t = __ffsll((long long)mm) - 1;
        mm &= mm - 1;
        if (rank < OUTK) {
            int i = lane * 64 + t;
            float4 bx = g_box[b][i];
            ((float4*)out)[b * OUTK + rank] = bx;
            out[BATCH * OUTK * 4 + b * OUTK + rank] = ss[i];
            out[BATCH * OUTK * 5 + b * OUTK + rank] = (float)g_label[b][i];
        }
        rank++;
    }

    int start = (total < OUTK) ? total : OUTK;
    for (int r2 = start + lane; r2 < OUTK; r2 += 32) {
        ((float4*)out)[b * OUTK + r2] = make_float4(0.f, 0.f, 0.f, 0.f);
        out[BATCH * OUTK * 4 + b * OUTK + r2] = 0.0f;
        out[BATCH * OUTK * 5 + b * OUTK + r2] = -1.0f;
    }
}

// ---------------- launch ----------------
extern "C" void kernel_launch(void* const* d_in, const int* in_sizes, int n_in,
                              void* d_out, int out_size) {
    const float* cls = (const float*)d_in[0];   // [16,2048,81]
    const float* reg = (const float*)d_in[1];   // [16,2048,320]
    const float* props = (const float*)d_in[2]; // [16,2048,4]
    const int* hw = (const int*)d_in[3];        // [16,2]
    float* out = (float*)d_out;

    cudaFuncSetAttribute(k_sort_decode,
                         cudaFuncAttributeMaxDynamicSharedMemorySize, CAP * 8);

    k_reset<<<1, 32>>>();
    k_softmax_compact<<<(BATCH * NPROP * 32) / 256, 256>>>(cls);
    k_sort_decode<<<BATCH, 1024, CAP * 8>>>(reg, props, hw);
    k_build_mask<<<dim3(KTOP / 64, BATCH), 256>>>();
    k_scan_out<<<BATCH, 32>>>(out);
}

// round 3
// speedup vs baseline: 3.5113x; 3.5113x over previous
#include <cuda_runtime.h>
#include <cstdint>

#define BATCH 16
#define NPROP 2048
#define NCLS 80
#define NCLS1 81
#define KTOP 2048
#define CAP 16384
#define SCORE_THR 0.05f
#define IOU_THR 0.5f
#define MAXR 4.135166556742356f
#define OUTK 100
#define BINS 2304
#define SCANN 4096
#define NMS_NT 1024
#define NMS_CH (KTOP / NMS_NT)

typedef unsigned long long ull;

// ---------------- device scratch ----------------
__device__ ull g_keys[BATCH][CAP];
__device__ int g_cnt[BATCH];
__device__ int g_hist[BATCH][BINS];
__device__ float g_score[BATCH][KTOP];
__device__ int g_label[BATCH][KTOP];
__device__ float4 g_box[BATCH][KTOP];
__device__ float4 g_sbox[BATCH][KTOP];

__device__ __forceinline__ int score_bin(unsigned u) {
    int bn = (int)(u >> 14) - 62770;
    return min(max(bn, 0), BINS - 1);
}

// ---------------- 0: reset counters + histogram ----------------
__global__ void k_reset() {
    int n = BATCH * BINS;
    for (int i = blockIdx.x * blockDim.x + threadIdx.x; i < n; i += gridDim.x * blockDim.x)
        ((int*)g_hist)[i] = 0;
    if (blockIdx.x == 0 && threadIdx.x < BATCH) g_cnt[threadIdx.x] = 0;
}

// ---------------- 1: softmax + threshold compaction + histogram ----------------
__global__ void k_softmax_compact(const float* __restrict__ cls) {
    int gw = (blockIdx.x * blockDim.x + threadIdx.x) >> 5;
    int lane = threadIdx.x & 31;
    if (gw >= BATCH * NPROP) return;
    int b = gw >> 11;
    int n = gw & (NPROP - 1);
    const float* x = cls + (size_t)gw * NCLS1;
    float v0 = x[lane];
    float v1 = x[lane + 32];
    float v2 = (lane < 17) ? x[lane + 64] : -3.4e38f;
    float m = fmaxf(fmaxf(v0, v1), v2);
#pragma unroll
    for (int o = 16; o > 0; o >>= 1) m = fmaxf(m, __shfl_xor_sync(0xffffffffu, m, o));
    float e0 = expf(v0 - m);
    float e1 = expf(v1 - m);
    float e2 = (lane < 17) ? expf(v2 - m) : 0.0f;
    float s = e0 + e1 + e2;
#pragma unroll
    for (int o = 16; o > 0; o >>= 1) s += __shfl_xor_sync(0xffffffffu, s, o);

    auto push = [&](bool cond, float p, unsigned idx) {
        unsigned mask = __ballot_sync(0xffffffffu, cond);
        if (cond) {
            unsigned u = __float_as_uint(p);
            atomicAdd(&g_hist[b][score_bin(u)], 1);
            int leader = __ffs(mask) - 1;
            int base = 0;
            if (lane == leader) base = atomicAdd(&g_cnt[b], __popc(mask));
            base = __shfl_sync(mask, base, leader);
            int pos = base + __popc(mask & ((1u << lane) - 1));
            if (pos < CAP)
                g_keys[b][pos] = ((ull)(~u) << 32) | idx;
        }
    };
    float p0 = e0 / s;
    push(p0 > SCORE_THR, p0, (unsigned)(n * NCLS + lane));
    float p1 = e1 / s;
    push(p1 > SCORE_THR, p1, (unsigned)(n * NCLS + lane + 32));
    float p2 = e2 / s;  // 0 for lane>=17
    push((lane < 16) && (p2 > SCORE_THR), p2, (unsigned)(n * NCLS + lane + 64));
}

// ---------------- 2: histogram-select + bitonic sort + decode ----------------
extern __shared__ ull sk[];
__global__ void k_sort_decode(const float* __restrict__ reg,
                              const float* __restrict__ props,
                              const int* __restrict__ hw) {
    int b = blockIdx.x;
    int tid = threadIdx.x;
    int nth = blockDim.x;
    int cnt = g_cnt[b];
    if (cnt > CAP) cnt = CAP;

    // --- suffix scan of histogram (ping-pong in dynamic smem) ---
    int* hA = (int*)sk;
    int* hB = hA + SCANN;
    for (int i = tid; i < SCANN; i += nth)
        hA[i] = (i < BINS) ? g_hist[b][i] : 0;
    __syncthreads();
    int* src = hA;
    int* dst = hB;
    for (int off = 1; off < SCANN; off <<= 1) {
        for (int i = tid; i < SCANN; i += nth) {
            int v = src[i];
            if (i + off < SCANN) v += src[i + off];
            dst[i] = v;
        }
        __syncthreads();
        int* t = src; src = dst; dst = t;
    }
    // src[i] = #candidates with bin >= i
    int target = min(cnt, KTOP);
    __shared__ int sB, selc;
    if (tid == 0) { sB = 0; selc = 0; }
    __syncthreads();
    for (int i = tid; i < BINS; i += nth)
        if (src[i] >= target) atomicMax(&sB, i);
    __syncthreads();
    int Bstar = sB;
    __syncthreads();  // done reading src — smem reused for keys

    // --- select candidates with bin >= Bstar ---
    for (int i = tid; i < cnt; i += nth) {
        ull key = g_keys[b][i];
        unsigned u = ~(unsigned)(key >> 32);
        if (score_bin(u) >= Bstar) {
            int pos = atomicAdd(&selc, 1);
            sk[pos] = key;
        }
    }
    __syncthreads();
    int S = selc;
    int P = KTOP;
    while (P < S) P <<= 1;  // <= CAP
    for (int i = tid; i < P; i += nth)
        if (i >= S) sk[i] = ~0ULL;
    __syncthreads();

    // --- bitonic sort of P keys ---
    for (int k = 2; k <= P; k <<= 1) {
        for (int j = k >> 1; j > 0; j >>= 1) {
            for (int i = tid; i < P; i += nth) {
                int ixj = i ^ j;
                if (ixj > i) {
                    ull a = sk[i], c = sk[ixj];
                    bool up = ((i & k) == 0);
                    if ((a > c) == up) { sk[i] = c; sk[ixj] = a; }
                }
            }
            __syncthreads();
        }
    }

    // --- decode top-2048 ---
    float h = (float)hw[b * 2];
    float w = (float)hw[b * 2 + 1];
    float offmul = fmaxf(w, h) + 1.0f;

    for (int i = tid; i < KTOP; i += nth) {
        ull key = sk[i];
        if (key == ~0ULL) {
            g_score[b][i] = -1.0f;
            g_label[b][i] = -1;
            g_box[b][i] = make_float4(0.f, 0.f, 0.f, 0.f);
            g_sbox[b][i] = make_float4(-1e9f, -1e9f, -1e9f, -1e9f);
            continue;
        }
        float p = __uint_as_float(~(unsigned)(key >> 32));
        unsigned idx = (unsigned)key;
        int n = (int)(idx / NCLS);
        int c = (int)(idx % NCLS);
        const float* pr = props + ((size_t)b * NPROP + n) * 4;
        float p0 = pr[0], p1 = pr[1], p2 = pr[2], p3 = pr[3];
        float px = (p0 + p2) * 0.5f;
        float py = (p1 + p3) * 0.5f;
        float pw = p2 - p0;
        float ph = p3 - p1;
        const float* dd = reg + ((size_t)b * NPROP + n) * (NCLS * 4) + c * 4;
        float dx = dd[0] * 0.1f;
        float dy = dd[1] * 0.1f;
        float dw = fminf(fmaxf(dd[2] * 0.2f, -MAXR), MAXR);
        float dh = fminf(fmaxf(dd[3] * 0.2f, -MAXR), MAXR);
        float gw = pw * expf(dw);
        float gh = ph * expf(dh);
        float gx = px + pw * dx;
        float gy = py + ph * dy;
        float x1 = fminf(fmaxf(gx - 0.5f * gw, 0.f), w);
        float y1 = fminf(fmaxf(gy - 0.5f * gh, 0.f), h);
        float x2 = fminf(fmaxf(gx + 0.5f * gw, 0.f), w);
        float y2 = fminf(fmaxf(gy + 0.5f * gh, 0.f), h);
        float off = (float)c * offmul;
        g_score[b][i] = p;
        g_label[b][i] = c;
        g_box[b][i] = make_float4(x1, y1, x2, y2);
        g_sbox[b][i] = make_float4(x1 + off, y1 + off, x2 + off, y2 + off);
    }
}

// ---------------- 3: fused greedy NMS + output (early exit at 100 keeps) ----------------
__global__ void __launch_bounds__(NMS_NT) k_nms_out(float* __restrict__ out) {
    int b = blockIdx.x;
    int tid = threadIdx.x;
    int lane = tid & 31;

    __shared__ float4 sb[KTOP];
    __shared__ float sarea[KTOP];
    __shared__ unsigned alive[KTOP / 32];
    __shared__ int s_keep[OUTK];
    __shared__ int s_next, s_kc, s_cur;

    if (tid == 0) { s_kc = 0; s_cur = -1; }
#pragma unroll
    for (int c = 0; c < NMS_CH; c++) {
        int j = tid + c * NMS_NT;
        float4 v = g_sbox[b][j];
        sb[j] = v;
        sarea[j] = fmaxf(v.z - v.x, 0.f) * fmaxf(v.w - v.y, 0.f);
        bool ok = g_score[b][j] > SCORE_THR;
        unsigned bal = __ballot_sync(0xffffffffu, ok);
        if (lane == 0) alive[j >> 5] = bal;
    }
    __syncthreads();

    for (;;) {
        // warp 0: find first alive index > s_cur
        if (tid < 32) {
            int cur = s_cur;
            ull ww = (ull)alive[2 * lane] | ((ull)alive[2 * lane + 1] << 32);
            int base = lane * 64;
            if (cur >= base) {
                int k = cur - base;
                if (k >= 63) ww = 0ULL;
                else ww &= ~((2ULL << k) - 1ULL);
            }
            unsigned bal = __ballot_sync(0xffffffffu, ww != 0ULL);
            int nxt = -1;
            if (bal) {
                int ln = __ffs(bal) - 1;
                ull w2 = __shfl_sync(0xffffffffu, ww, ln);
                nxt = ln * 64 + __ffsll((long long)w2) - 1;
            }
            if (lane == 0) s_next = nxt;
        }
        __syncthreads();
        int i = s_next;
        if (i < 0) break;
        if (tid == 0) { s_keep[s_kc] = i; s_kc++; s_cur = i; }
        __syncthreads();
        if (s_kc >= OUTK) break;

        float4 a = sb[i];
        float areaA = sarea[i];
#pragma unroll
        for (int c = 0; c < NMS_CH; c++) {
            int j = tid + c * NMS_NT;
            float4 q = sb[j];
            float ltx = fmaxf(a.x, q.x);
            float lty = fmaxf(a.y, q.y);
            float rbx = fminf(a.z, q.z);
            float rby = fminf(a.w, q.w);
            float iw = fmaxf(rbx - ltx, 0.f);
            float ih = fmaxf(rby - lty, 0.f);
            float inter = iw * ih;
            float uni = areaA + sarea[j] - inter;
            bool sup = (j > i) && (uni > 0.f) && (inter > IOU_THR * uni);
            unsigned bal = __ballot_sync(0xffffffffu, sup);
            if (lane == 0 && bal) alive[j >> 5] &= ~bal;
        }
        __syncthreads();
    }
    __syncthreads();

    int kc = s_kc;
    for (int r = tid; r < OUTK; r += NMS_NT) {
        if (r < kc) {
            int i = s_keep[r];
            ((float4*)out)[b * OUTK + r] = g_box[b][i];
            out[BATCH * OUTK * 4 + b * OUTK + r] = g_score[b][i];
            out[BATCH * OUTK * 5 + b * OUTK + r] = (float)g_label[b][i];
        } else {
            ((float4*)out)[b * OUTK + r] = make_float4(0.f, 0.f, 0.f, 0.f);
            out[BATCH * OUTK * 4 + b * OUTK + r] = 0.0f;
            out[BATCH * OUTK * 5 + b * OUTK + r] = -1.0f;
        }
    }
}

// ---------------- launch ----------------
extern "C" void kernel_launch(void* const* d_in, const int* in_sizes, int n_in,
                              void* d_out, int out_size) {
    const float* cls = (const float*)d_in[0];   // [16,2048,81]
    const float* reg = (const float*)d_in[1];   // [16,2048,320]
    const float* props = (const float*)d_in[2]; // [16,2048,4]
    const int* hw = (const int*)d_in[3];        // [16,2]
    float* out = (float*)d_out;

    cudaFuncSetAttribute(k_sort_decode,
                         cudaFuncAttributeMaxDynamicSharedMemorySize, CAP * 8);

    k_reset<<<32, 1024>>>();
    k_softmax_compact<<<(BATCH * NPROP * 32) / 256, 256>>>(cls);
    k_sort_decode<<<BATCH, 1024, CAP * 8>>>(reg, props, hw);
    k_nms_out<<<BATCH, NMS_NT>>>(out);
}

// round 4
// speedup vs baseline: 4.8293x; 1.3754x over previous
#include <cuda_runtime.h>
#include <cstdint>

#define BATCH 16
#define NPROP 2048
#define NCLS 80
#define NCLS1 81
#define KTOP 2048
#define CAP 16384
#define SCORE_THR 0.05f
#define IOU_THR 0.5f
#define MAXR 4.135166556742356f
#define OUTK 100
#define BINS 2304
#define SCANN 4096
#define SLOTS 4096
#define NT 1024

typedef unsigned long long ull;

// ---------------- device scratch ----------------
__device__ ull g_keys[BATCH][CAP];
__device__ int g_cnt[BATCH];
__device__ int g_hist[BATCH][BINS];

__device__ __forceinline__ int score_bin(unsigned u) {
    int bn = (int)(u >> 14) - 62770;
    return min(max(bn, 0), BINS - 1);
}

// ---------------- 0: reset ----------------
__global__ void k_reset() {
    int n = BATCH * BINS;
    for (int i = blockIdx.x * blockDim.x + threadIdx.x; i < n; i += gridDim.x * blockDim.x)
        ((int*)g_hist)[i] = 0;
    if (blockIdx.x == 0 && threadIdx.x < BATCH) g_cnt[threadIdx.x] = 0;
}

// ---------------- 1: softmax + threshold compaction + histogram ----------------
__global__ void k_softmax_compact(const float* __restrict__ cls) {
    int gw = (blockIdx.x * blockDim.x + threadIdx.x) >> 5;
    int lane = threadIdx.x & 31;
    if (gw >= BATCH * NPROP) return;
    int b = gw >> 11;
    int n = gw & (NPROP - 1);
    const float* x = cls + (size_t)gw * NCLS1;
    float v0 = x[lane];
    float v1 = x[lane + 32];
    float v2 = (lane < 17) ? x[lane + 64] : -3.4e38f;
    float m = fmaxf(fmaxf(v0, v1), v2);
#pragma unroll
    for (int o = 16; o > 0; o >>= 1) m = fmaxf(m, __shfl_xor_sync(0xffffffffu, m, o));
    float e0 = expf(v0 - m);
    float e1 = expf(v1 - m);
    float e2 = (lane < 17) ? expf(v2 - m) : 0.0f;
    float s = e0 + e1 + e2;
#pragma unroll
    for (int o = 16; o > 0; o >>= 1) s += __shfl_xor_sync(0xffffffffu, s, o);

    auto push = [&](bool cond, float p, unsigned idx) {
        unsigned mask = __ballot_sync(0xffffffffu, cond);
        if (cond) {
            unsigned u = __float_as_uint(p);
            atomicAdd(&g_hist[b][score_bin(u)], 1);
            int leader = __ffs(mask) - 1;
            int base = 0;
            if (lane == leader) base = atomicAdd(&g_cnt[b], __popc(mask));
            base = __shfl_sync(mask, base, leader);
            int pos = base + __popc(mask & ((1u << lane) - 1));
            if (pos < CAP)
                g_keys[b][pos] = ((ull)(~u) << 32) | idx;
        }
    };
    float p0 = e0 / s;
    push(p0 > SCORE_THR, p0, (unsigned)(n * NCLS + lane));
    float p1 = e1 / s;
    push(p1 > SCORE_THR, p1, (unsigned)(n * NCLS + lane + 32));
    float p2 = e2 / s;  // 0 for lane>=17
    push((lane < 16) && (p2 > SCORE_THR), p2, (unsigned)(n * NCLS + lane + 64));
}

// ---------------- 2: fused counting-sort + decode + greedy NMS + output ----------------
// dynamic smem layout (bytes):
//   [0        , 32768 )  ull  skey[SLOTS]
//   [32768    , 49152 )  int  scanA[SCANN]
//   [49152    , 65536 )  int  scanB[SCANN]
//   [65536    , 74752 )  int  base[BINS]
//   [74752    , 83968 )  int  ctr[BINS]
//   [83968    , 116736)  float4 sbox[KTOP]   (class-offset boxes)
//   [116736   , 149504)  float4 sbxout[KTOP] (clipped boxes for output)
//   [149504   , 157696)  float  sarea[KTOP]
#define SMEM_DYN 157696
extern __shared__ char dyn[];

__global__ void __launch_bounds__(NT) k_fused(const float* __restrict__ reg,
                                              const float* __restrict__ props,
                                              const int* __restrict__ hw,
                                              float* __restrict__ out) {
    int b = blockIdx.x;
    int tid = threadIdx.x;
    int lane = tid & 31;

    ull* skey = (ull*)dyn;
    int* scanA = (int*)(dyn + 32768);
    int* scanB = (int*)(dyn + 49152);
    int* base = (int*)(dyn + 65536);
    int* ctr = (int*)(dyn + 74752);
    float4* sbox = (float4*)(dyn + 83968);
    float4* sbxout = (float4*)(dyn + 116736);
    float* sarea = (float*)(dyn + 149504);

    __shared__ ull alivemask[KTOP / 64];
    __shared__ int s_keep[OUTK];

    // ---- suffix scan of histogram ----
    for (int i = tid; i < SCANN; i += NT)
        scanA[i] = (i < BINS) ? g_hist[b][i] : 0;
    __syncthreads();
    int* src = scanA;
    int* dst = scanB;
    for (int off = 1; off < SCANN; off <<= 1) {
        for (int i = tid; i < SCANN; i += NT) {
            int v = src[i];
            if (i + off < SCANN) v += src[i + off];
            dst[i] = v;
        }
        __syncthreads();
        int* t = src; src = dst; dst = t;
    }
    // src[i] = #candidates with bin >= i
    int S_total = src[0];

    // ---- base offsets, counters, slot init ----
    for (int i = tid; i < BINS; i += NT) {
        base[i] = (i + 1 < SCANN) ? src[i + 1] : 0;
        ctr[i] = 0;
    }
    for (int i = tid; i < SLOTS; i += NT) skey[i] = ~0ULL;
    __syncthreads();

    // ---- scatter keys to sorted-by-bin slots ----
    int cnt = g_cnt[b];
    if (cnt > CAP) cnt = CAP;
    for (int i = tid; i < cnt; i += NT) {
        ull key = g_keys[b][i];
        unsigned u = ~(unsigned)(key >> 32);
        int bb = score_bin(u);
        int pos = base[bb] + atomicAdd(&ctr[bb], 1);
        if (pos < SLOTS) skey[pos] = key;
    }
    __syncthreads();

    // ---- per-bin insertion sort (fix within-bin order by full key) ----
    for (int bb = tid; bb < BINS; bb += NT) {
        int st = base[bb];
        if (st >= KTOP) continue;        // segment entirely beyond top-2048
        int n = ctr[bb];
        if (n <= 1) continue;
        int en = st + n;
        if (en > SLOTS) en = SLOTS;
        for (int k = st + 1; k < en; k++) {
            ull v = skey[k];
            int m2 = k - 1;
            while (m2 >= st && skey[m2] > v) { skey[m2 + 1] = skey[m2]; m2--; }
            skey[m2 + 1] = v;
        }
    }
    __syncthreads();

    int validcnt = min(min(S_total, cnt), KTOP);

    // ---- decode top-2048 ----
    float h = (float)hw[b * 2];
    float w = (float)hw[b * 2 + 1];
    float offmul = fmaxf(w, h) + 1.0f;

    for (int i = tid; i < KTOP; i += NT) {
        if (i >= validcnt) {
            sbox[i] = make_float4(-1e9f, -1e9f, -1e9f, -1e9f);
            sbxout[i] = make_float4(0.f, 0.f, 0.f, 0.f);
            sarea[i] = 0.f;
            continue;
        }
        ull key = skey[i];
        unsigned idx = (unsigned)key;
        int n = (int)(idx / NCLS);
        int c = (int)(idx % NCLS);
        const float* pr = props + ((size_t)b * NPROP + n) * 4;
        float p0 = pr[0], p1 = pr[1], p2 = pr[2], p3 = pr[3];
        float px = (p0 + p2) * 0.5f;
        float py = (p1 + p3) * 0.5f;
        float pw = p2 - p0;
        float ph = p3 - p1;
        const float* dd = reg + ((size_t)b * NPROP + n) * (NCLS * 4) + c * 4;
        float dx = dd[0] * 0.1f;
        float dy = dd[1] * 0.1f;
        float dw = fminf(fmaxf(dd[2] * 0.2f, -MAXR), MAXR);
        float dh = fminf(fmaxf(dd[3] * 0.2f, -MAXR), MAXR);
        float gw = pw * expf(dw);
        float gh = ph * expf(dh);
        float gx = px + pw * dx;
        float gy = py + ph * dy;
        float x1 = fminf(fmaxf(gx - 0.5f * gw, 0.f), w);
        float y1 = fminf(fmaxf(gy - 0.5f * gh, 0.f), h);
        float x2 = fminf(fmaxf(gx + 0.5f * gw, 0.f), w);
        float y2 = fminf(fmaxf(gy + 0.5f * gh, 0.f), h);
        float off = (float)c * offmul;
        sbxout[i] = make_float4(x1, y1, x2, y2);
        float4 sbv = make_float4(x1 + off, y1 + off, x2 + off, y2 + off);
        sbox[i] = sbv;
        sarea[i] = fmaxf(sbv.z - sbv.x, 0.f) * fmaxf(sbv.w - sbv.y, 0.f);
    }

    // ---- alive init ----
    unsigned* a32 = (unsigned*)alivemask;
    {
        unsigned b1 = __ballot_sync(0xffffffffu, tid < validcnt);
        if (lane == 0) a32[tid >> 5] = b1;
        unsigned b2 = __ballot_sync(0xffffffffu, tid + 1024 < validcnt);
        if (lane == 0) a32[32 + (tid >> 5)] = b2;
    }
    __syncthreads();

    // ---- greedy NMS: 1 barrier / iteration, redundant per-warp search ----
    int cur = -1;
    int kc = 0;
    for (;;) {
        // every warp: find first alive index > cur (lane L covers bits [64L,64L+64))
        ull ww = ((ull)a32[2 * lane]) | (((ull)a32[2 * lane + 1]) << 32);
        int basebit = lane << 6;
        if (cur >= basebit) {
            int k = cur - basebit;
            ww = (k >= 63) ? 0ULL : (ww & ~((2ULL << k) - 1ULL));
        }
        unsigned bal = __ballot_sync(0xffffffffu, ww != 0ULL);
        int i = -1;
        if (bal) {
            int ln = __ffs(bal) - 1;
            ull w2 = __shfl_sync(0xffffffffu, ww, ln);
            i = (ln << 6) + __ffsll((long long)w2) - 1;
        }
        if (i < 0) break;
        if (tid == 0) s_keep[kc] = i;
        kc++;
        cur = i;
        if (kc >= OUTK) break;

        float4 A = sbox[i];
        float areaA = sarea[i];
        {
            int j = tid;
            float4 q = sbox[j];
            float ltx = fmaxf(A.x, q.x);
            float lty = fmaxf(A.y, q.y);
            float rbx = fminf(A.z, q.z);
            float rby = fminf(A.w, q.w);
            float inter = fmaxf(rbx - ltx, 0.f) * fmaxf(rby - lty, 0.f);
            float uni = areaA + sarea[j] - inter;
            bool sup = (j > i) && (uni > 0.f) && (inter > IOU_THR * uni);
            unsigned sb_ = __ballot_sync(0xffffffffu, sup);
            if (lane == 0) a32[tid >> 5] &= ~sb_;
        }
        {
            int j = tid + 1024;
            float4 q = sbox[j];
            float ltx = fmaxf(A.x, q.x);
            float lty = fmaxf(A.y, q.y);
            float rbx = fminf(A.z, q.z);
            float rby = fminf(A.w, q.w);
            float inter = fmaxf(rbx - ltx, 0.f) * fmaxf(rby - lty, 0.f);
            float uni = areaA + sarea[j] - inter;
            bool sup = (j > i) && (uni > 0.f) && (inter > IOU_THR * uni);
            unsigned sb_ = __ballot_sync(0xffffffffu, sup);
            if (lane == 0) a32[32 + (tid >> 5)] &= ~sb_;
        }
        __syncthreads();
    }
    __syncthreads();  // s_keep visibility

    // ---- output ----
    for (int r = tid; r < OUTK; r += NT) {
        if (r < kc) {
            int i = s_keep[r];
            ull key = skey[i];
            ((float4*)out)[b * OUTK + r] = sbxout[i];
            out[BATCH * OUTK * 4 + b * OUTK + r] = __uint_as_float(~(unsigned)(key >> 32));
            out[BATCH * OUTK * 5 + b * OUTK + r] = (float)((unsigned)key % NCLS);
        } else {
            ((float4*)out)[b * OUTK + r] = make_float4(0.f, 0.f, 0.f, 0.f);
            out[BATCH * OUTK * 4 + b * OUTK + r] = 0.0f;
            out[BATCH * OUTK * 5 + b * OUTK + r] = -1.0f;
        }
    }
}

// ---------------- launch ----------------
extern "C" void kernel_launch(void* const* d_in, const int* in_sizes, int n_in,
                              void* d_out, int out_size) {
    const float* cls = (const float*)d_in[0];   // [16,2048,81]
    const float* reg = (const float*)d_in[1];   // [16,2048,320]
    const float* props = (const float*)d_in[2]; // [16,2048,4]
    const int* hw = (const int*)d_in[3];        // [16,2]
    float* out = (float*)d_out;

    cudaFuncSetAttribute(k_fused,
                         cudaFuncAttributeMaxDynamicSharedMemorySize, SMEM_DYN);

    k_reset<<<32, 1024>>>();
    k_softmax_compact<<<(BATCH * NPROP * 32) / 256, 256>>>(cls);
    k_fused<<<BATCH, NT, SMEM_DYN>>>(reg, props, hw, out);
}